// round 1
// baseline (speedup 1.0000x reference)
#include <cuda_runtime.h>
#include <math.h>

// Problem constants
#define C_DIM   1024
#define HEADS   16
#define HD      64
#define BATCH   2
#define SEQ     2048
#define M_ROWS  (BATCH*SEQ)        // 4096

// Scratch (device globals: no allocation allowed)
__device__ float g_qkv[(size_t)M_ROWS * 3 * C_DIM];          // [4096, 3072]
__device__ float g_Q[(size_t)BATCH*HEADS*SEQ*HD];            // [B,H,N,D]
__device__ float g_K[(size_t)BATCH*HEADS*SEQ*HD];
__device__ float g_V[(size_t)BATCH*HEADS*SEQ*HD];
__device__ float g_attn[(size_t)M_ROWS * C_DIM];             // [B,N,H*D]

// ---------------------------------------------------------------------------
// GEMM (NT): C[M,N] = A[M,K] * B[N,K]^T (+ bias[N]); M,N % 128 == 0, K % 16 == 0
// ---------------------------------------------------------------------------
#define BM 128
#define BN 128
#define BKK 16

__global__ __launch_bounds__(256, 2)
void gemm_nt(const float* __restrict__ A, const float* __restrict__ B,
             float* __restrict__ C, int M, int N, int K,
             const float* __restrict__ bias)
{
    __shared__ float As[BKK][BM];
    __shared__ float Bs[BKK][BN];

    const int tid = threadIdx.x;
    const int tx  = tid & 15;
    const int ty  = tid >> 4;
    const int m0  = blockIdx.y * BM;
    const int n0  = blockIdx.x * BN;

    float acc[8][8];
#pragma unroll
    for (int i = 0; i < 8; i++)
#pragma unroll
        for (int j = 0; j < 8; j++) acc[i][j] = 0.f;

    for (int k0 = 0; k0 < K; k0 += BKK) {
#pragma unroll
        for (int it = 0; it < 2; it++) {
            int e   = tid + it * 256;     // 0..511
            int row = e >> 2;             // 0..127
            int kq  = (e & 3) << 2;       // 0,4,8,12
            float4 va = *(const float4*)&A[(size_t)(m0 + row) * K + k0 + kq];
            As[kq + 0][row] = va.x; As[kq + 1][row] = va.y;
            As[kq + 2][row] = va.z; As[kq + 3][row] = va.w;
            float4 vb = *(const float4*)&B[(size_t)(n0 + row) * K + k0 + kq];
            Bs[kq + 0][row] = vb.x; Bs[kq + 1][row] = vb.y;
            Bs[kq + 2][row] = vb.z; Bs[kq + 3][row] = vb.w;
        }
        __syncthreads();

#pragma unroll
        for (int kk = 0; kk < BKK; kk++) {
            float4 a0 = *(const float4*)&As[kk][ty * 8];
            float4 a1 = *(const float4*)&As[kk][ty * 8 + 4];
            float4 b0 = *(const float4*)&Bs[kk][tx * 8];
            float4 b1 = *(const float4*)&Bs[kk][tx * 8 + 4];
            float a[8] = {a0.x, a0.y, a0.z, a0.w, a1.x, a1.y, a1.z, a1.w};
            float b[8] = {b0.x, b0.y, b0.z, b0.w, b1.x, b1.y, b1.z, b1.w};
#pragma unroll
            for (int i = 0; i < 8; i++)
#pragma unroll
                for (int j = 0; j < 8; j++)
                    acc[i][j] = fmaf(a[i], b[j], acc[i][j]);
        }
        __syncthreads();
    }

    float bv[8];
#pragma unroll
    for (int j = 0; j < 8; j++) bv[j] = bias ? bias[n0 + tx * 8 + j] : 0.f;

#pragma unroll
    for (int i = 0; i < 8; i++) {
        int row = m0 + ty * 8 + i;
        float4 r0, r1;
        r0.x = acc[i][0] + bv[0]; r0.y = acc[i][1] + bv[1];
        r0.z = acc[i][2] + bv[2]; r0.w = acc[i][3] + bv[3];
        r1.x = acc[i][4] + bv[4]; r1.y = acc[i][5] + bv[5];
        r1.z = acc[i][6] + bv[6]; r1.w = acc[i][7] + bv[7];
        *(float4*)&C[(size_t)row * N + n0 + tx * 8]     = r0;
        *(float4*)&C[(size_t)row * N + n0 + tx * 8 + 4] = r1;
    }
}

// ---------------------------------------------------------------------------
// RoPE + transpose: qkv [4096, 3072] -> Q,K (roped), V  in [B,H,N,D]
// ---------------------------------------------------------------------------
__global__ void rope_transpose(const float* __restrict__ qkv,
                               float* __restrict__ Q, float* __restrict__ K,
                               float* __restrict__ V)
{
    int idx = blockIdx.x * blockDim.x + threadIdx.x;   // over B*H*N*D
    if (idx >= BATCH * HEADS * SEQ * HD) return;
    int d = idx & (HD - 1);
    int n = (idx >> 6) & (SEQ - 1);
    int h = (idx >> 17) & (HEADS - 1);
    int b = idx >> 21;

    const size_t mrow = (size_t)(b * SEQ + n) * (3 * C_DIM);
    const int col = h * HD + d;

    float qv = qkv[mrow + col];
    float kv = qkv[mrow + C_DIM + col];
    float vv = qkv[mrow + 2 * C_DIM + col];

    int i = d & 31;
    // inv_freq exact-to-fp32, phase multiplied in fp32 (matches reference), trig in double
    float inv_freq = (float)pow(10000.0, -(double)i / 32.0);
    float phase = (float)n * inv_freq;
    float c = (float)cos((double)phase);
    float s = (float)sin((double)phase);

    float qp = (d < 32) ? -qkv[mrow + col + 32] : qkv[mrow + col - 32];
    float kp = (d < 32) ? -qkv[mrow + C_DIM + col + 32] : qkv[mrow + C_DIM + col - 32];

    size_t o = ((size_t)(b * HEADS + h) * SEQ + n) * HD + d;
    Q[o] = qv * c + qp * s;
    K[o] = kv * c + kp * s;
    V[o] = vv;
}

// ---------------------------------------------------------------------------
// Flash attention: 64x64 Q/KV tiles, online softmax, fp32.
// grid = (SEQ/64, HEADS, BATCH), 256 threads.
// Output written as [B, N, H, D] (i.e. [B,N,C]) for the final GEMM.
// ---------------------------------------------------------------------------
#define ATTN_SMEM_FLOATS (64*64*3 + 64*65)
#define ATTN_SMEM_BYTES  (ATTN_SMEM_FLOATS * 4)

__global__ __launch_bounds__(256)
void attn_kernel(const float* __restrict__ Q, const float* __restrict__ K,
                 const float* __restrict__ V, float* __restrict__ Out)
{
    extern __shared__ float sm[];
    float* Qst = sm;                  // [64][64] d-major: Qst[d*64 + row]
    float* Kst = Qst + 64 * 64;       // [64][64] d-major
    float* Vs  = Kst + 64 * 64;       // [64][64] natural: Vs[k*64 + d]
    float* Ps  = Vs  + 64 * 64;       // [64][65] q-major padded

    const int tid = threadIdx.x;
    const int tx = tid & 15, ty = tid >> 4;
    const int b = blockIdx.z, h = blockIdx.y;
    const int q0 = blockIdx.x * 64;

    const float* Qb = Q + (size_t)(b * HEADS + h) * SEQ * HD;
    const float* Kb = K + (size_t)(b * HEADS + h) * SEQ * HD;
    const float* Vb = V + (size_t)(b * HEADS + h) * SEQ * HD;

    // Load Q tile transposed
    for (int i = tid; i < 64 * 16; i += 256) {
        int r = i >> 4;
        int c4 = (i & 15) << 2;
        float4 v = *(const float4*)&Qb[(size_t)(q0 + r) * HD + c4];
        Qst[(c4 + 0) * 64 + r] = v.x;
        Qst[(c4 + 1) * 64 + r] = v.y;
        Qst[(c4 + 2) * 64 + r] = v.z;
        Qst[(c4 + 3) * 64 + r] = v.w;
    }

    float m_i[4], l_i[4], o[4][4];
#pragma unroll
    for (int i = 0; i < 4; i++) {
        m_i[i] = -1e30f; l_i[i] = 0.f;
#pragma unroll
        for (int j = 0; j < 4; j++) o[i][j] = 0.f;
    }
    __syncthreads();

    const float scale = 0.125f;   // 1/sqrt(64)

    for (int k0 = 0; k0 < SEQ; k0 += 64) {
        // Load K (transposed) and V (natural)
        for (int i = tid; i < 64 * 16; i += 256) {
            int r = i >> 4;
            int c4 = (i & 15) << 2;
            float4 kv = *(const float4*)&Kb[(size_t)(k0 + r) * HD + c4];
            Kst[(c4 + 0) * 64 + r] = kv.x;
            Kst[(c4 + 1) * 64 + r] = kv.y;
            Kst[(c4 + 2) * 64 + r] = kv.z;
            Kst[(c4 + 3) * 64 + r] = kv.w;
            float4 vv = *(const float4*)&Vb[(size_t)(k0 + r) * HD + c4];
            *(float4*)&Vs[r * 64 + c4] = vv;
        }
        __syncthreads();

        // S = Q K^T
        float s[4][4];
#pragma unroll
        for (int i = 0; i < 4; i++)
#pragma unroll
            for (int j = 0; j < 4; j++) s[i][j] = 0.f;

#pragma unroll 8
        for (int d = 0; d < 64; d++) {
            float4 a = *(const float4*)&Qst[d * 64 + ty * 4];
            float4 bb = *(const float4*)&Kst[d * 64 + tx * 4];
            float av[4] = {a.x, a.y, a.z, a.w};
            float bvv[4] = {bb.x, bb.y, bb.z, bb.w};
#pragma unroll
            for (int i = 0; i < 4; i++)
#pragma unroll
                for (int j = 0; j < 4; j++)
                    s[i][j] = fmaf(av[i], bvv[j], s[i][j]);
        }

        // Scale + online softmax
        float mnew[4], alpha[4], rs[4];
#pragma unroll
        for (int i = 0; i < 4; i++) {
            float rm = -1e30f;
#pragma unroll
            for (int j = 0; j < 4; j++) {
                s[i][j] *= scale;
                rm = fmaxf(rm, s[i][j]);
            }
#pragma unroll
            for (int off = 8; off >= 1; off >>= 1)
                rm = fmaxf(rm, __shfl_xor_sync(0xffffffffu, rm, off));
            mnew[i] = fmaxf(m_i[i], rm);
            alpha[i] = expf(m_i[i] - mnew[i]);
            float sum = 0.f;
#pragma unroll
            for (int j = 0; j < 4; j++) {
                float p = expf(s[i][j] - mnew[i]);
                s[i][j] = p;
                sum += p;
            }
#pragma unroll
            for (int off = 8; off >= 1; off >>= 1)
                sum += __shfl_xor_sync(0xffffffffu, sum, off);
            rs[i] = sum;
            l_i[i] = l_i[i] * alpha[i] + rs[i];
            m_i[i] = mnew[i];
#pragma unroll
            for (int j = 0; j < 4; j++) o[i][j] *= alpha[i];
        }

        // Store P (padded) for PV GEMM
#pragma unroll
        for (int i = 0; i < 4; i++)
#pragma unroll
            for (int j = 0; j < 4; j++)
                Ps[(ty * 4 + i) * 65 + tx * 4 + j] = s[i][j];
        __syncthreads();

        // O += P @ V
#pragma unroll 8
        for (int k = 0; k < 64; k++) {
            float a0 = Ps[(ty * 4 + 0) * 65 + k];
            float a1 = Ps[(ty * 4 + 1) * 65 + k];
            float a2 = Ps[(ty * 4 + 2) * 65 + k];
            float a3 = Ps[(ty * 4 + 3) * 65 + k];
            float4 vv = *(const float4*)&Vs[k * 64 + tx * 4];
            o[0][0] = fmaf(a0, vv.x, o[0][0]); o[0][1] = fmaf(a0, vv.y, o[0][1]);
            o[0][2] = fmaf(a0, vv.z, o[0][2]); o[0][3] = fmaf(a0, vv.w, o[0][3]);
            o[1][0] = fmaf(a1, vv.x, o[1][0]); o[1][1] = fmaf(a1, vv.y, o[1][1]);
            o[1][2] = fmaf(a1, vv.z, o[1][2]); o[1][3] = fmaf(a1, vv.w, o[1][3]);
            o[2][0] = fmaf(a2, vv.x, o[2][0]); o[2][1] = fmaf(a2, vv.y, o[2][1]);
            o[2][2] = fmaf(a2, vv.z, o[2][2]); o[2][3] = fmaf(a2, vv.w, o[2][3]);
            o[3][0] = fmaf(a3, vv.x, o[3][0]); o[3][1] = fmaf(a3, vv.y, o[3][1]);
            o[3][2] = fmaf(a3, vv.z, o[3][2]); o[3][3] = fmaf(a3, vv.w, o[3][3]);
        }
        __syncthreads();
    }

    // Epilogue: normalize, write as [B, N, H, D]
#pragma unroll
    for (int i = 0; i < 4; i++) {
        float inv = 1.0f / l_i[i];
        int qrow = q0 + ty * 4 + i;
        float4 r;
        r.x = o[i][0] * inv; r.y = o[i][1] * inv;
        r.z = o[i][2] * inv; r.w = o[i][3] * inv;
        size_t oidx = ((size_t)(b * SEQ + qrow) * HEADS + h) * HD + tx * 4;
        *(float4*)&Out[oidx] = r;
    }
}

// ---------------------------------------------------------------------------
extern "C" void kernel_launch(void* const* d_in, const int* in_sizes, int n_in,
                              void* d_out, int out_size)
{
    const float* x    = (const float*)d_in[0];   // [2,2048,1024]
    const float* Wqkv = (const float*)d_in[1];   // [3072,1024]
    const float* Wout = (const float*)d_in[2];   // [1024,1024]
    const float* bout = (const float*)d_in[3];   // [1024]
    float* out = (float*)d_out;                  // [2,2048,1024]

    float *qkv, *Q, *K, *V, *attn;
    cudaGetSymbolAddress((void**)&qkv,  g_qkv);
    cudaGetSymbolAddress((void**)&Q,    g_Q);
    cudaGetSymbolAddress((void**)&K,    g_K);
    cudaGetSymbolAddress((void**)&V,    g_V);
    cudaGetSymbolAddress((void**)&attn, g_attn);

    // 1) QKV projection: [4096,3072] = x[4096,1024] @ Wqkv^T
    gemm_nt<<<dim3(3 * C_DIM / BN, M_ROWS / BM), 256>>>(
        x, Wqkv, qkv, M_ROWS, 3 * C_DIM, C_DIM, nullptr);

    // 2) RoPE + transpose into [B,H,N,D]
    {
        int total = BATCH * HEADS * SEQ * HD;
        rope_transpose<<<(total + 255) / 256, 256>>>(qkv, Q, K, V);
    }

    // 3) Flash attention -> [B,N,C]
    cudaFuncSetAttribute(attn_kernel,
                         cudaFuncAttributeMaxDynamicSharedMemorySize,
                         ATTN_SMEM_BYTES);
    attn_kernel<<<dim3(SEQ / 64, HEADS, BATCH), 256, ATTN_SMEM_BYTES>>>(
        Q, K, V, attn);

    // 4) Output projection: out = attn @ Wout^T + bout
    gemm_nt<<<dim3(C_DIM / BN, M_ROWS / BM), 256>>>(
        attn, Wout, out, M_ROWS, C_DIM, C_DIM, bout);
}

// round 2
// speedup vs baseline: 4.3214x; 4.3214x over previous
#include <cuda_runtime.h>
#include <math.h>

// Problem constants
#define C_DIM   1024
#define HEADS   16
#define HD      64
#define BATCH   2
#define SEQ     2048
#define M_ROWS  (BATCH*SEQ)        // 4096

// Scratch (device globals: no allocation allowed)
__device__ float g_qkv[(size_t)M_ROWS * 3 * C_DIM];          // [4096, 3072]
__device__ float g_Q[(size_t)BATCH*HEADS*SEQ*HD];            // [B,H,N,D]
__device__ float g_K[(size_t)BATCH*HEADS*SEQ*HD];
__device__ float g_V[(size_t)BATCH*HEADS*SEQ*HD];
__device__ float g_attn[(size_t)M_ROWS * C_DIM];             // [B,N,H*D]
__device__ float g_cos[SEQ * 32];
__device__ float g_sin[SEQ * 32];

// ---------------------------------------------------------------------------
// tf32 helpers
// ---------------------------------------------------------------------------
__device__ __forceinline__ unsigned f2tf(float x) {
    unsigned r;
    asm("cvt.rna.tf32.f32 %0, %1;" : "=r"(r) : "f"(x));
    return r;
}

__device__ __forceinline__ void mma_tf32(float* d, const unsigned* a, const unsigned* b) {
    asm volatile(
        "mma.sync.aligned.m16n8k8.row.col.f32.tf32.tf32.f32 "
        "{%0,%1,%2,%3}, {%4,%5,%6,%7}, {%8,%9}, {%0,%1,%2,%3};\n"
        : "+f"(d[0]), "+f"(d[1]), "+f"(d[2]), "+f"(d[3])
        : "r"(a[0]), "r"(a[1]), "r"(a[2]), "r"(a[3]), "r"(b[0]), "r"(b[1]));
}

// ---------------------------------------------------------------------------
// tf32 GEMM (NT): C[M,N] = A[M,K] * B[N,K]^T (+ bias)
// Block 128x128, BK=32, 256 threads (8 warps: 2m x 4n, warp tile 64x32)
// ---------------------------------------------------------------------------
#define GBM 128
#define GBN 128
#define GBK 32
#define GPAD 4

__global__ __launch_bounds__(256)
void gemm_tf32_nt(const float* __restrict__ A, const float* __restrict__ B,
                  float* __restrict__ C, int M, int N, int K,
                  const float* __restrict__ bias)
{
    __shared__ unsigned As[GBM][GBK + GPAD];   // [m][k]
    __shared__ unsigned Bs[GBN][GBK + GPAD];   // [n][k]

    const int tid  = threadIdx.x;
    const int lane = tid & 31;
    const int warp = tid >> 5;
    const int wm   = (warp >> 2) * 64;
    const int wn   = (warp & 3) * 32;
    const int m0   = blockIdx.y * GBM;
    const int n0   = blockIdx.x * GBN;
    const int lg   = lane >> 2;   // group id 0..7
    const int lt   = lane & 3;    // thread in group

    float acc[4][4][4];
#pragma unroll
    for (int mt = 0; mt < 4; mt++)
#pragma unroll
        for (int nt = 0; nt < 4; nt++)
#pragma unroll
            for (int j = 0; j < 4; j++) acc[mt][nt][j] = 0.f;

    for (int k0 = 0; k0 < K; k0 += GBK) {
#pragma unroll
        for (int i = 0; i < 4; i++) {
            int e  = tid + i * 256;
            int r  = e >> 3;
            int kq = (e & 7) << 2;
            float4 va = *(const float4*)&A[(size_t)(m0 + r) * K + k0 + kq];
            uint4 ua = make_uint4(f2tf(va.x), f2tf(va.y), f2tf(va.z), f2tf(va.w));
            *(uint4*)&As[r][kq] = ua;
            float4 vb = *(const float4*)&B[(size_t)(n0 + r) * K + k0 + kq];
            uint4 ub = make_uint4(f2tf(vb.x), f2tf(vb.y), f2tf(vb.z), f2tf(vb.w));
            *(uint4*)&Bs[r][kq] = ub;
        }
        __syncthreads();

#pragma unroll
        for (int ks = 0; ks < GBK; ks += 8) {
            unsigned af[4][4], bf[4][2];
#pragma unroll
            for (int mt = 0; mt < 4; mt++) {
                int r = wm + mt * 16 + lg;
                af[mt][0] = As[r][ks + lt];
                af[mt][1] = As[r + 8][ks + lt];
                af[mt][2] = As[r][ks + lt + 4];
                af[mt][3] = As[r + 8][ks + lt + 4];
            }
#pragma unroll
            for (int nt = 0; nt < 4; nt++) {
                int r = wn + nt * 8 + lg;
                bf[nt][0] = Bs[r][ks + lt];
                bf[nt][1] = Bs[r][ks + lt + 4];
            }
#pragma unroll
            for (int mt = 0; mt < 4; mt++)
#pragma unroll
                for (int nt = 0; nt < 4; nt++)
                    mma_tf32(acc[mt][nt], af[mt], bf[nt]);
        }
        __syncthreads();
    }

#pragma unroll
    for (int mt = 0; mt < 4; mt++) {
#pragma unroll
        for (int nt = 0; nt < 4; nt++) {
            int r = m0 + wm + mt * 16 + lg;
            int c = n0 + wn + nt * 8 + (lt << 1);
            float b0 = bias ? bias[c] : 0.f;
            float b1 = bias ? bias[c + 1] : 0.f;
            float2 v0 = make_float2(acc[mt][nt][0] + b0, acc[mt][nt][1] + b1);
            float2 v1 = make_float2(acc[mt][nt][2] + b0, acc[mt][nt][3] + b1);
            *(float2*)&C[(size_t)r * N + c]       = v0;
            *(float2*)&C[(size_t)(r + 8) * N + c] = v1;
        }
    }
}

// ---------------------------------------------------------------------------
// RoPE cos/sin table (accurate fp64 trig, tiny kernel)
// ---------------------------------------------------------------------------
__global__ void rope_table()
{
    int idx = blockIdx.x * blockDim.x + threadIdx.x;  // over SEQ*32
    if (idx >= SEQ * 32) return;
    int i = idx & 31;
    int n = idx >> 5;
    float inv_freq = (float)pow(10000.0, -(double)i / 32.0);
    float phase = (float)n * inv_freq;
    g_cos[idx] = (float)cos((double)phase);
    g_sin[idx] = (float)sin((double)phase);
}

// ---------------------------------------------------------------------------
// RoPE + transpose: qkv [4096, 3072] -> Q,K (roped), V  in [B,H,N,D]
// ---------------------------------------------------------------------------
__global__ void rope_transpose(const float* __restrict__ qkv,
                               float* __restrict__ Q, float* __restrict__ K,
                               float* __restrict__ V)
{
    int idx = blockIdx.x * blockDim.x + threadIdx.x;   // over B*H*N*D
    if (idx >= BATCH * HEADS * SEQ * HD) return;
    int d = idx & (HD - 1);
    int n = (idx >> 6) & (SEQ - 1);
    int h = (idx >> 17) & (HEADS - 1);
    int b = idx >> 21;

    const size_t mrow = (size_t)(b * SEQ + n) * (3 * C_DIM);
    const int col = h * HD + d;

    float qv = qkv[mrow + col];
    float kv = qkv[mrow + C_DIM + col];
    float vv = qkv[mrow + 2 * C_DIM + col];

    int i = d & 31;
    float c = g_cos[n * 32 + i];
    float s = g_sin[n * 32 + i];

    float qp = (d < 32) ? -qkv[mrow + col + 32] : qkv[mrow + col - 32];
    float kp = (d < 32) ? -qkv[mrow + C_DIM + col + 32] : qkv[mrow + C_DIM + col - 32];

    size_t o = ((size_t)(b * HEADS + h) * SEQ + n) * HD + d;
    Q[o] = qv * c + qp * s;
    K[o] = kv * c + kp * s;
    V[o] = vv;
}

// ---------------------------------------------------------------------------
// Flash attention with tf32 mma: 64 Q x 64 KV tiles, 4 warps (128 thr).
// Each warp owns 16 q-rows. Output [B, N, H*D].
// ---------------------------------------------------------------------------
#define ASTRIDE 72
#define ATTN_SMEM_BYTES (4 * 64 * ASTRIDE * 4)

__global__ __launch_bounds__(128)
void attn_tf32(const float* __restrict__ Q, const float* __restrict__ K,
               const float* __restrict__ V, float* __restrict__ Out)
{
    extern __shared__ unsigned sm[];
    unsigned* Qs = sm;                      // [64][72] tf32, row=q, col=d
    unsigned* Ks = Qs + 64 * ASTRIDE;       // [64][72] row=kv, col=d
    unsigned* Vs = Ks + 64 * ASTRIDE;       // [64][72] row=kv, col=d
    unsigned* Ps = Vs + 64 * ASTRIDE;       // [64][72] row=q, col=kv

    const int tid  = threadIdx.x;
    const int lane = tid & 31;
    const int warp = tid >> 5;
    const int lg   = lane >> 2;
    const int lt   = lane & 3;
    const int b = blockIdx.z, h = blockIdx.y;
    const int q0 = blockIdx.x * 64;
    const int qr = warp * 16;               // warp's q-row base in tile

    const float* Qb = Q + (size_t)(b * HEADS + h) * SEQ * HD;
    const float* Kb = K + (size_t)(b * HEADS + h) * SEQ * HD;
    const float* Vb = V + (size_t)(b * HEADS + h) * SEQ * HD;

    // Load Q tile (cvt to tf32)
#pragma unroll
    for (int i = 0; i < 8; i++) {
        int e = tid + i * 128;
        int r = e >> 4, c4 = (e & 15) << 2;
        float4 v = *(const float4*)&Qb[(size_t)(q0 + r) * HD + c4];
        uint4 u = make_uint4(f2tf(v.x), f2tf(v.y), f2tf(v.z), f2tf(v.w));
        *(uint4*)&Qs[r * ASTRIDE + c4] = u;
    }

    float o[8][4];
#pragma unroll
    for (int nt = 0; nt < 8; nt++)
#pragma unroll
        for (int j = 0; j < 4; j++) o[nt][j] = 0.f;
    float m_lo = -1e30f, m_hi = -1e30f, l_lo = 0.f, l_hi = 0.f;

    __syncthreads();

    for (int k0 = 0; k0 < SEQ; k0 += 64) {
        // Load K, V tiles (cvt to tf32)
#pragma unroll
        for (int i = 0; i < 8; i++) {
            int e = tid + i * 128;
            int r = e >> 4, c4 = (e & 15) << 2;
            float4 kv = *(const float4*)&Kb[(size_t)(k0 + r) * HD + c4];
            *(uint4*)&Ks[r * ASTRIDE + c4] =
                make_uint4(f2tf(kv.x), f2tf(kv.y), f2tf(kv.z), f2tf(kv.w));
            float4 vv = *(const float4*)&Vb[(size_t)(k0 + r) * HD + c4];
            *(uint4*)&Vs[r * ASTRIDE + c4] =
                make_uint4(f2tf(vv.x), f2tf(vv.y), f2tf(vv.z), f2tf(vv.w));
        }
        __syncthreads();

        // ---- S = Q K^T  (warp: 16 x 64) ----
        float s[8][4];
#pragma unroll
        for (int nt = 0; nt < 8; nt++)
#pragma unroll
            for (int j = 0; j < 4; j++) s[nt][j] = 0.f;

#pragma unroll
        for (int ks = 0; ks < 8; ks++) {
            unsigned af[4];
            int ar = (qr + lg) * ASTRIDE + ks * 8 + lt;
            af[0] = Qs[ar];
            af[1] = Qs[ar + 8 * ASTRIDE];
            af[2] = Qs[ar + 4];
            af[3] = Qs[ar + 8 * ASTRIDE + 4];
#pragma unroll
            for (int nt = 0; nt < 8; nt++) {
                unsigned bf[2];
                int br = (nt * 8 + lg) * ASTRIDE + ks * 8 + lt;
                bf[0] = Ks[br];
                bf[1] = Ks[br + 4];
                mma_tf32(s[nt], af, bf);
            }
        }

        // ---- online softmax on fragments ----
        const float scale = 0.125f;
        float rmax_lo = -1e30f, rmax_hi = -1e30f;
#pragma unroll
        for (int nt = 0; nt < 8; nt++) {
            s[nt][0] *= scale; s[nt][1] *= scale;
            s[nt][2] *= scale; s[nt][3] *= scale;
            rmax_lo = fmaxf(rmax_lo, fmaxf(s[nt][0], s[nt][1]));
            rmax_hi = fmaxf(rmax_hi, fmaxf(s[nt][2], s[nt][3]));
        }
        rmax_lo = fmaxf(rmax_lo, __shfl_xor_sync(0xffffffffu, rmax_lo, 1));
        rmax_lo = fmaxf(rmax_lo, __shfl_xor_sync(0xffffffffu, rmax_lo, 2));
        rmax_hi = fmaxf(rmax_hi, __shfl_xor_sync(0xffffffffu, rmax_hi, 1));
        rmax_hi = fmaxf(rmax_hi, __shfl_xor_sync(0xffffffffu, rmax_hi, 2));

        float mn_lo = fmaxf(m_lo, rmax_lo);
        float mn_hi = fmaxf(m_hi, rmax_hi);
        float alpha_lo = __expf(m_lo - mn_lo);
        float alpha_hi = __expf(m_hi - mn_hi);
        m_lo = mn_lo; m_hi = mn_hi;

        float sum_lo = 0.f, sum_hi = 0.f;
#pragma unroll
        for (int nt = 0; nt < 8; nt++) {
            float p0 = __expf(s[nt][0] - m_lo);
            float p1 = __expf(s[nt][1] - m_lo);
            float p2 = __expf(s[nt][2] - m_hi);
            float p3 = __expf(s[nt][3] - m_hi);
            sum_lo += p0 + p1;
            sum_hi += p2 + p3;
            int pr = (qr + lg) * ASTRIDE + nt * 8 + (lt << 1);
            *(uint2*)&Ps[pr]                = make_uint2(f2tf(p0), f2tf(p1));
            *(uint2*)&Ps[pr + 8 * ASTRIDE]  = make_uint2(f2tf(p2), f2tf(p3));
            o[nt][0] *= alpha_lo; o[nt][1] *= alpha_lo;
            o[nt][2] *= alpha_hi; o[nt][3] *= alpha_hi;
        }
        sum_lo += __shfl_xor_sync(0xffffffffu, sum_lo, 1);
        sum_lo += __shfl_xor_sync(0xffffffffu, sum_lo, 2);
        sum_hi += __shfl_xor_sync(0xffffffffu, sum_hi, 1);
        sum_hi += __shfl_xor_sync(0xffffffffu, sum_hi, 2);
        l_lo = l_lo * alpha_lo + sum_lo;
        l_hi = l_hi * alpha_hi + sum_hi;

        __syncwarp();   // Ps rows owned by this warp only

        // ---- O += P V  (warp: 16 x 64) ----
#pragma unroll
        for (int ks = 0; ks < 8; ks++) {
            unsigned pf[4];
            int pr = (qr + lg) * ASTRIDE + ks * 8 + lt;
            pf[0] = Ps[pr];
            pf[1] = Ps[pr + 8 * ASTRIDE];
            pf[2] = Ps[pr + 4];
            pf[3] = Ps[pr + 8 * ASTRIDE + 4];
#pragma unroll
            for (int nt = 0; nt < 8; nt++) {
                unsigned vf[2];
                int vr = (ks * 8 + lt) * ASTRIDE + nt * 8 + lg;
                vf[0] = Vs[vr];
                vf[1] = Vs[vr + 4 * ASTRIDE];
                mma_tf32(o[nt], pf, vf);
            }
        }
        __syncthreads();
    }

    // ---- epilogue: normalize, write [B, N, H*D] ----
    float inv_lo = 1.0f / l_lo;
    float inv_hi = 1.0f / l_hi;
#pragma unroll
    for (int nt = 0; nt < 8; nt++) {
        int r = q0 + qr + lg;
        int c = h * HD + nt * 8 + (lt << 1);
        float2 v0 = make_float2(o[nt][0] * inv_lo, o[nt][1] * inv_lo);
        float2 v1 = make_float2(o[nt][2] * inv_hi, o[nt][3] * inv_hi);
        *(float2*)&Out[(size_t)(b * SEQ + r) * C_DIM + c]       = v0;
        *(float2*)&Out[(size_t)(b * SEQ + r + 8) * C_DIM + c]   = v1;
    }
}

// ---------------------------------------------------------------------------
extern "C" void kernel_launch(void* const* d_in, const int* in_sizes, int n_in,
                              void* d_out, int out_size)
{
    const float* x    = (const float*)d_in[0];   // [2,2048,1024]
    const float* Wqkv = (const float*)d_in[1];   // [3072,1024]
    const float* Wout = (const float*)d_in[2];   // [1024,1024]
    const float* bout = (const float*)d_in[3];   // [1024]
    float* out = (float*)d_out;                  // [2,2048,1024]

    float *qkv, *Q, *K, *V, *attn;
    cudaGetSymbolAddress((void**)&qkv,  g_qkv);
    cudaGetSymbolAddress((void**)&Q,    g_Q);
    cudaGetSymbolAddress((void**)&K,    g_K);
    cudaGetSymbolAddress((void**)&V,    g_V);
    cudaGetSymbolAddress((void**)&attn, g_attn);

    // 0) RoPE tables
    rope_table<<<(SEQ * 32 + 255) / 256, 256>>>();

    // 1) QKV projection (tf32): [4096,3072] = x @ Wqkv^T
    gemm_tf32_nt<<<dim3(3 * C_DIM / GBN, M_ROWS / GBM), 256>>>(
        x, Wqkv, qkv, M_ROWS, 3 * C_DIM, C_DIM, nullptr);

    // 2) RoPE + transpose into [B,H,N,D]
    {
        int total = BATCH * HEADS * SEQ * HD;
        rope_transpose<<<(total + 255) / 256, 256>>>(qkv, Q, K, V);
    }

    // 3) Flash attention (tf32 mma) -> [B,N,C]
    cudaFuncSetAttribute(attn_tf32,
                         cudaFuncAttributeMaxDynamicSharedMemorySize,
                         ATTN_SMEM_BYTES);
    attn_tf32<<<dim3(SEQ / 64, HEADS, BATCH), 128, ATTN_SMEM_BYTES>>>(
        Q, K, V, attn);

    // 4) Output projection (tf32): out = attn @ Wout^T + bout
    gemm_tf32_nt<<<dim3(C_DIM / GBN, M_ROWS / GBM), 256>>>(
        attn, Wout, out, M_ROWS, C_DIM, C_DIM, bout);
}

// round 3
// speedup vs baseline: 4.9438x; 1.1440x over previous
#include <cuda_runtime.h>
#include <math.h>

// Problem constants
#define C_DIM   1024
#define HEADS   16
#define HD      64
#define BATCH   2
#define SEQ     2048
#define M_ROWS  (BATCH*SEQ)        // 4096

// Scratch (device globals: no allocation allowed)
__device__ float g_qkv[(size_t)M_ROWS * 3 * C_DIM];          // [4096, 3072]
__device__ float g_Q[(size_t)BATCH*HEADS*SEQ*HD];            // [B,H,N,D]
__device__ float g_K[(size_t)BATCH*HEADS*SEQ*HD];
__device__ float g_V[(size_t)BATCH*HEADS*SEQ*HD];
__device__ float g_attn[(size_t)M_ROWS * C_DIM];             // [B,N,H*D]
__device__ float g_cos[SEQ * 32];
__device__ float g_sin[SEQ * 32];

// ---------------------------------------------------------------------------
// tf32 helpers
// ---------------------------------------------------------------------------
__device__ __forceinline__ unsigned f2tf(float x) {
    unsigned r;
    asm("cvt.rna.tf32.f32 %0, %1;" : "=r"(r) : "f"(x));
    return r;
}

__device__ __forceinline__ void mma_tf32(float* d, const unsigned* a, const unsigned* b) {
    asm volatile(
        "mma.sync.aligned.m16n8k8.row.col.f32.tf32.tf32.f32 "
        "{%0,%1,%2,%3}, {%4,%5,%6,%7}, {%8,%9}, {%0,%1,%2,%3};\n"
        : "+f"(d[0]), "+f"(d[1]), "+f"(d[2]), "+f"(d[3])
        : "r"(a[0]), "r"(a[1]), "r"(a[2]), "r"(a[3]), "r"(b[0]), "r"(b[1]));
}

// ---------------------------------------------------------------------------
// tf32 GEMM (NT): C[M,N] = A[M,K] * B[N,K]^T (+ bias)
// Block 128x128, BK=32, 256 threads (8 warps: 2m x 4n, warp tile 64x32)
// ---------------------------------------------------------------------------
#define GBM 128
#define GBN 128
#define GBK 32
#define GPAD 4

__global__ __launch_bounds__(256)
void gemm_tf32_nt(const float* __restrict__ A, const float* __restrict__ B,
                  float* __restrict__ C, int M, int N, int K,
                  const float* __restrict__ bias)
{
    __shared__ unsigned As[GBM][GBK + GPAD];   // [m][k]
    __shared__ unsigned Bs[GBN][GBK + GPAD];   // [n][k]

    const int tid  = threadIdx.x;
    const int lane = tid & 31;
    const int warp = tid >> 5;
    const int wm   = (warp >> 2) * 64;
    const int wn   = (warp & 3) * 32;
    const int m0   = blockIdx.y * GBM;
    const int n0   = blockIdx.x * GBN;
    const int lg   = lane >> 2;   // group id 0..7
    const int lt   = lane & 3;    // thread in group

    float acc[4][4][4];
#pragma unroll
    for (int mt = 0; mt < 4; mt++)
#pragma unroll
        for (int nt = 0; nt < 4; nt++)
#pragma unroll
            for (int j = 0; j < 4; j++) acc[mt][nt][j] = 0.f;

    for (int k0 = 0; k0 < K; k0 += GBK) {
#pragma unroll
        for (int i = 0; i < 4; i++) {
            int e  = tid + i * 256;
            int r  = e >> 3;
            int kq = (e & 7) << 2;
            float4 va = *(const float4*)&A[(size_t)(m0 + r) * K + k0 + kq];
            uint4 ua = make_uint4(f2tf(va.x), f2tf(va.y), f2tf(va.z), f2tf(va.w));
            *(uint4*)&As[r][kq] = ua;
            float4 vb = *(const float4*)&B[(size_t)(n0 + r) * K + k0 + kq];
            uint4 ub = make_uint4(f2tf(vb.x), f2tf(vb.y), f2tf(vb.z), f2tf(vb.w));
            *(uint4*)&Bs[r][kq] = ub;
        }
        __syncthreads();

#pragma unroll
        for (int ks = 0; ks < GBK; ks += 8) {
            unsigned af[4][4], bf[4][2];
#pragma unroll
            for (int mt = 0; mt < 4; mt++) {
                int r = wm + mt * 16 + lg;
                af[mt][0] = As[r][ks + lt];
                af[mt][1] = As[r + 8][ks + lt];
                af[mt][2] = As[r][ks + lt + 4];
                af[mt][3] = As[r + 8][ks + lt + 4];
            }
#pragma unroll
            for (int nt = 0; nt < 4; nt++) {
                int r = wn + nt * 8 + lg;
                bf[nt][0] = Bs[r][ks + lt];
                bf[nt][1] = Bs[r][ks + lt + 4];
            }
#pragma unroll
            for (int mt = 0; mt < 4; mt++)
#pragma unroll
                for (int nt = 0; nt < 4; nt++)
                    mma_tf32(acc[mt][nt], af[mt], bf[nt]);
        }
        __syncthreads();
    }

#pragma unroll
    for (int mt = 0; mt < 4; mt++) {
#pragma unroll
        for (int nt = 0; nt < 4; nt++) {
            int r = m0 + wm + mt * 16 + lg;
            int c = n0 + wn + nt * 8 + (lt << 1);
            float b0 = bias ? bias[c] : 0.f;
            float b1 = bias ? bias[c + 1] : 0.f;
            float2 v0 = make_float2(acc[mt][nt][0] + b0, acc[mt][nt][1] + b1);
            float2 v1 = make_float2(acc[mt][nt][2] + b0, acc[mt][nt][3] + b1);
            *(float2*)&C[(size_t)r * N + c]       = v0;
            *(float2*)&C[(size_t)(r + 8) * N + c] = v1;
        }
    }
}

// ---------------------------------------------------------------------------
// RoPE cos/sin table (accurate fp64 trig, tiny kernel)
// ---------------------------------------------------------------------------
__global__ void rope_table()
{
    int idx = blockIdx.x * blockDim.x + threadIdx.x;  // over SEQ*32
    if (idx >= SEQ * 32) return;
    int i = idx & 31;
    int n = idx >> 5;
    float inv_freq = (float)pow(10000.0, -(double)i / 32.0);
    float phase = (float)n * inv_freq;
    g_cos[idx] = (float)cos((double)phase);
    g_sin[idx] = (float)sin((double)phase);
}

// ---------------------------------------------------------------------------
// RoPE + transpose: qkv [4096, 3072] -> Q,K (roped), V  in [B,H,N,D]
// ---------------------------------------------------------------------------
__global__ void rope_transpose(const float* __restrict__ qkv,
                               float* __restrict__ Q, float* __restrict__ K,
                               float* __restrict__ V)
{
    int idx = blockIdx.x * blockDim.x + threadIdx.x;   // over B*H*N*D
    if (idx >= BATCH * HEADS * SEQ * HD) return;
    int d = idx & (HD - 1);
    int n = (idx >> 6) & (SEQ - 1);
    int h = (idx >> 17) & (HEADS - 1);
    int b = idx >> 21;

    const size_t mrow = (size_t)(b * SEQ + n) * (3 * C_DIM);
    const int col = h * HD + d;

    float qv = qkv[mrow + col];
    float kv = qkv[mrow + C_DIM + col];
    float vv = qkv[mrow + 2 * C_DIM + col];

    int i = d & 31;
    float c = g_cos[n * 32 + i];
    float s = g_sin[n * 32 + i];

    float qp = (d < 32) ? -qkv[mrow + col + 32] : qkv[mrow + col - 32];
    float kp = (d < 32) ? -qkv[mrow + C_DIM + col + 32] : qkv[mrow + C_DIM + col - 32];

    size_t o = ((size_t)(b * HEADS + h) * SEQ + n) * HD + d;
    Q[o] = qv * c + qp * s;
    K[o] = kv * c + kp * s;
    V[o] = vv;
}

// ---------------------------------------------------------------------------
// Flash attention v2 (tf32 mma):
//  - 128 Q rows per block, 8 warps (256 thr), warp owns 16 q-rows
//  - 64-row KV tiles
//  - P never goes through smem: accumulator->A-fragment conversion by shfl
//  - Q/K smem stride 68 words, V stride 72 (both conflict-free for frag reads)
// ---------------------------------------------------------------------------
#define QTILE 128
#define KTILE 64
#define QKST  68
#define VST   72
#define ATTN_SMEM_BYTES ((QTILE*QKST + KTILE*QKST + KTILE*VST) * 4)

__global__ __launch_bounds__(256)
void attn_tf32(const float* __restrict__ Q, const float* __restrict__ K,
               const float* __restrict__ V, float* __restrict__ Out)
{
    extern __shared__ unsigned sm[];
    unsigned* Qs = sm;                       // [128][68] tf32, row=q, col=d
    unsigned* Ks = Qs + QTILE * QKST;        // [64][68]  row=kv, col=d
    unsigned* Vs = Ks + KTILE * QKST;        // [64][72]  row=kv, col=d

    const int tid  = threadIdx.x;
    const int lane = tid & 31;
    const int warp = tid >> 5;
    const int lg   = lane >> 2;
    const int lt   = lane & 3;
    const int b = blockIdx.z, h = blockIdx.y;
    const int q0 = blockIdx.x * QTILE;
    const int qr = warp * 16;                // warp's q-row base in tile

    const float* Qb = Q + (size_t)(b * HEADS + h) * SEQ * HD;
    const float* Kb = K + (size_t)(b * HEADS + h) * SEQ * HD;
    const float* Vb = V + (size_t)(b * HEADS + h) * SEQ * HD;

    // Load Q tile (cvt to tf32)
#pragma unroll
    for (int i = 0; i < 8; i++) {
        int e = tid + i * 256;
        int r = e >> 4, c4 = (e & 15) << 2;
        float4 v = *(const float4*)&Qb[(size_t)(q0 + r) * HD + c4];
        *(uint4*)&Qs[r * QKST + c4] =
            make_uint4(f2tf(v.x), f2tf(v.y), f2tf(v.z), f2tf(v.w));
    }

    float o[8][4];
#pragma unroll
    for (int nt = 0; nt < 8; nt++)
#pragma unroll
        for (int j = 0; j < 4; j++) o[nt][j] = 0.f;
    float m_lo = -1e30f, m_hi = -1e30f, l_lo = 0.f, l_hi = 0.f;

    __syncthreads();

    const int psrc = lg * 4 + (lt >> 1);     // shuffle source lane
    const bool podd = (lt & 1);

    for (int k0 = 0; k0 < SEQ; k0 += KTILE) {
        // Load K, V tiles (cvt to tf32)
#pragma unroll
        for (int i = 0; i < 4; i++) {
            int e = tid + i * 256;
            int r = e >> 4, c4 = (e & 15) << 2;
            float4 kv = *(const float4*)&Kb[(size_t)(k0 + r) * HD + c4];
            *(uint4*)&Ks[r * QKST + c4] =
                make_uint4(f2tf(kv.x), f2tf(kv.y), f2tf(kv.z), f2tf(kv.w));
            float4 vv = *(const float4*)&Vb[(size_t)(k0 + r) * HD + c4];
            *(uint4*)&Vs[r * VST + c4] =
                make_uint4(f2tf(vv.x), f2tf(vv.y), f2tf(vv.z), f2tf(vv.w));
        }
        __syncthreads();

        // ---- S = Q K^T  (warp: 16 x 64) ----
        float s[8][4];
#pragma unroll
        for (int nt = 0; nt < 8; nt++)
#pragma unroll
            for (int j = 0; j < 4; j++) s[nt][j] = 0.f;

#pragma unroll
        for (int ks = 0; ks < 8; ks++) {
            unsigned af[4];
            int ar = (qr + lg) * QKST + ks * 8 + lt;
            af[0] = Qs[ar];
            af[1] = Qs[ar + 8 * QKST];
            af[2] = Qs[ar + 4];
            af[3] = Qs[ar + 8 * QKST + 4];
#pragma unroll
            for (int nt = 0; nt < 8; nt++) {
                unsigned bf[2];
                int br = (nt * 8 + lg) * QKST + ks * 8 + lt;
                bf[0] = Ks[br];
                bf[1] = Ks[br + 4];
                mma_tf32(s[nt], af, bf);
            }
        }

        // ---- online softmax on fragments ----
        const float scale = 0.125f;
        float rmax_lo = -1e30f, rmax_hi = -1e30f;
#pragma unroll
        for (int nt = 0; nt < 8; nt++) {
            s[nt][0] *= scale; s[nt][1] *= scale;
            s[nt][2] *= scale; s[nt][3] *= scale;
            rmax_lo = fmaxf(rmax_lo, fmaxf(s[nt][0], s[nt][1]));
            rmax_hi = fmaxf(rmax_hi, fmaxf(s[nt][2], s[nt][3]));
        }
        rmax_lo = fmaxf(rmax_lo, __shfl_xor_sync(0xffffffffu, rmax_lo, 1));
        rmax_lo = fmaxf(rmax_lo, __shfl_xor_sync(0xffffffffu, rmax_lo, 2));
        rmax_hi = fmaxf(rmax_hi, __shfl_xor_sync(0xffffffffu, rmax_hi, 1));
        rmax_hi = fmaxf(rmax_hi, __shfl_xor_sync(0xffffffffu, rmax_hi, 2));

        float mn_lo = fmaxf(m_lo, rmax_lo);
        float mn_hi = fmaxf(m_hi, rmax_hi);
        float alpha_lo = __expf(m_lo - mn_lo);
        float alpha_hi = __expf(m_hi - mn_hi);
        m_lo = mn_lo; m_hi = mn_hi;

        float sum_lo = 0.f, sum_hi = 0.f;
#pragma unroll
        for (int nt = 0; nt < 8; nt++) {
            s[nt][0] = __expf(s[nt][0] - m_lo);
            s[nt][1] = __expf(s[nt][1] - m_lo);
            s[nt][2] = __expf(s[nt][2] - m_hi);
            s[nt][3] = __expf(s[nt][3] - m_hi);
            sum_lo += s[nt][0] + s[nt][1];
            sum_hi += s[nt][2] + s[nt][3];
            o[nt][0] *= alpha_lo; o[nt][1] *= alpha_lo;
            o[nt][2] *= alpha_hi; o[nt][3] *= alpha_hi;
        }
        sum_lo += __shfl_xor_sync(0xffffffffu, sum_lo, 1);
        sum_lo += __shfl_xor_sync(0xffffffffu, sum_lo, 2);
        sum_hi += __shfl_xor_sync(0xffffffffu, sum_hi, 1);
        sum_hi += __shfl_xor_sync(0xffffffffu, sum_hi, 2);
        l_lo = l_lo * alpha_lo + sum_lo;
        l_hi = l_hi * alpha_hi + sum_hi;

        // ---- O += P V : P accumulator -> A-fragment via shfl, no smem ----
#pragma unroll
        for (int ks = 0; ks < 8; ks++) {
            float e0 = __shfl_sync(0xffffffffu, s[ks][0], psrc);
            float q0v = __shfl_sync(0xffffffffu, s[ks][1], psrc);
            float e1 = __shfl_sync(0xffffffffu, s[ks][2], psrc);
            float q1v = __shfl_sync(0xffffffffu, s[ks][3], psrc);
            float e2 = __shfl_sync(0xffffffffu, s[ks][0], psrc + 2);
            float q2v = __shfl_sync(0xffffffffu, s[ks][1], psrc + 2);
            float e3 = __shfl_sync(0xffffffffu, s[ks][2], psrc + 2);
            float q3v = __shfl_sync(0xffffffffu, s[ks][3], psrc + 2);
            unsigned pf[4];
            pf[0] = f2tf(podd ? q0v : e0);   // P[lg   ][8ks+lt  ]
            pf[1] = f2tf(podd ? q1v : e1);   // P[lg+8 ][8ks+lt  ]
            pf[2] = f2tf(podd ? q2v : e2);   // P[lg   ][8ks+lt+4]
            pf[3] = f2tf(podd ? q3v : e3);   // P[lg+8 ][8ks+lt+4]
#pragma unroll
            for (int nt = 0; nt < 8; nt++) {
                unsigned vf[2];
                int vr = (ks * 8 + lt) * VST + nt * 8 + lg;
                vf[0] = Vs[vr];
                vf[1] = Vs[vr + 4 * VST];
                mma_tf32(o[nt], pf, vf);
            }
        }
        __syncthreads();
    }

    // ---- epilogue: normalize, write [B, N, H*D] ----
    float inv_lo = 1.0f / l_lo;
    float inv_hi = 1.0f / l_hi;
#pragma unroll
    for (int nt = 0; nt < 8; nt++) {
        int r = q0 + qr + lg;
        int c = h * HD + nt * 8 + (lt << 1);
        float2 v0 = make_float2(o[nt][0] * inv_lo, o[nt][1] * inv_lo);
        float2 v1 = make_float2(o[nt][2] * inv_hi, o[nt][3] * inv_hi);
        *(float2*)&Out[(size_t)(b * SEQ + r) * C_DIM + c]       = v0;
        *(float2*)&Out[(size_t)(b * SEQ + r + 8) * C_DIM + c]   = v1;
    }
}

// ---------------------------------------------------------------------------
extern "C" void kernel_launch(void* const* d_in, const int* in_sizes, int n_in,
                              void* d_out, int out_size)
{
    const float* x    = (const float*)d_in[0];   // [2,2048,1024]
    const float* Wqkv = (const float*)d_in[1];   // [3072,1024]
    const float* Wout = (const float*)d_in[2];   // [1024,1024]
    const float* bout = (const float*)d_in[3];   // [1024]
    float* out = (float*)d_out;                  // [2,2048,1024]

    float *qkv, *Q, *K, *V, *attn;
    cudaGetSymbolAddress((void**)&qkv,  g_qkv);
    cudaGetSymbolAddress((void**)&Q,    g_Q);
    cudaGetSymbolAddress((void**)&K,    g_K);
    cudaGetSymbolAddress((void**)&V,    g_V);
    cudaGetSymbolAddress((void**)&attn, g_attn);

    // 0) RoPE tables
    rope_table<<<(SEQ * 32 + 255) / 256, 256>>>();

    // 1) QKV projection (tf32): [4096,3072] = x @ Wqkv^T
    gemm_tf32_nt<<<dim3(3 * C_DIM / GBN, M_ROWS / GBM), 256>>>(
        x, Wqkv, qkv, M_ROWS, 3 * C_DIM, C_DIM, nullptr);

    // 2) RoPE + transpose into [B,H,N,D]
    {
        int total = BATCH * HEADS * SEQ * HD;
        rope_transpose<<<(total + 255) / 256, 256>>>(qkv, Q, K, V);
    }

    // 3) Flash attention v2 (tf32 mma, shfl P-conversion) -> [B,N,C]
    cudaFuncSetAttribute(attn_tf32,
                         cudaFuncAttributeMaxDynamicSharedMemorySize,
                         ATTN_SMEM_BYTES);
    attn_tf32<<<dim3(SEQ / QTILE, HEADS, BATCH), 256, ATTN_SMEM_BYTES>>>(
        Q, K, V, attn);

    // 4) Output projection (tf32): out = attn @ Wout^T + bout
    gemm_tf32_nt<<<dim3(C_DIM / GBN, M_ROWS / GBM), 256>>>(
        attn, Wout, out, M_ROWS, C_DIM, C_DIM, bout);
}